// round 6
// baseline (speedup 1.0000x reference)
#include <cuda_runtime.h>
#include <cuda_bf16.h>

// Problem constants
#define Bx 4
#define Cx 3
#define Hx 224
#define Wx 224
#define Kx 196
#define Ex 768
#define HW (Hx * Wx)               // 50176
#define BK (Bx * Kx)               // 784

#define BPB 49                     // accumulate blocks per batch
#define NBLK (Bx * BPB)            // 196 total blocks
#define TA 256
#define PIX_PER_BLOCK (TA * 4)     // 1024; 49*1024 = HW exactly

#define ROWS_PER_BLOCK (BK / NBLK) // 4
#define COLS_PER_THREAD (Ex / TA)  // 3

// Pooled sums: one 128-byte row per (b,k) so rows spread across L2 slices.
// Only the first float4 of each row is used ({c0,c1,c2,pad}).
// Zero at module load; phase 2 re-zeroes consumed rows each call.
#define ROW_F4 8                   // 8 float4 = 128 B
__device__ float4 g_pool4[BK * ROW_F4];

// Grid barrier: monotone epoch counter (never reset; u64 cannot overflow).
__device__ unsigned long long g_bar;

__device__ __forceinline__ void red_add_v4(float4* p, float x, float y, float z) {
    asm volatile("red.global.add.v4.f32 [%0], {%1, %2, %3, %4};"
                 :: "l"(p), "f"(x), "f"(y), "f"(z), "f"(0.0f) : "memory");
}

__device__ __forceinline__ float4 ldcg4(const float4* p) {
    float4 v;
    asm volatile("ld.global.cg.v4.f32 {%0,%1,%2,%3}, [%4];"
                 : "=f"(v.x), "=f"(v.y), "=f"(v.z), "=f"(v.w) : "l"(p));
    return v;
}

__global__ void fused_kernel(const float* __restrict__ img,
                             const int* __restrict__ seg,
                             const float* __restrict__ Wmat,
                             const float* __restrict__ bias,
                             float* __restrict__ out) {
    const int tid = threadIdx.x;
    const int b   = blockIdx.x / BPB;
    const int blk = blockIdx.x % BPB;

    // ---------------- Phase 1: segment-sum via vector global reductions ----
    const int p0 = blk * PIX_PER_BLOCK + tid * 4;
    const float* img_b = img + (size_t)b * Cx * HW;
    const int*   seg_b = seg + (size_t)b * HW;

    int4   s  = *(const int4*)  (seg_b + p0);
    float4 v0 = *(const float4*)(img_b + p0);
    float4 v1 = *(const float4*)(img_b + p0 + HW);
    float4 v2 = *(const float4*)(img_b + p0 + 2 * HW);

    float4* pool_b = g_pool4 + (size_t)b * Kx * ROW_F4;
    red_add_v4(pool_b + s.x * ROW_F4, v0.x, v1.x, v2.x);
    red_add_v4(pool_b + s.y * ROW_F4, v0.y, v1.y, v2.y);
    red_add_v4(pool_b + s.z * ROW_F4, v0.z, v1.z, v2.z);
    red_add_v4(pool_b + s.w * ROW_F4, v0.w, v1.w, v2.w);

    // ---------------- Grid barrier ----------------
    __threadfence();                       // REDs visible before arrival RMW
    __syncthreads();                       // whole block arrived at fence point
    if (tid == 0) {
        unsigned long long old = atomicAdd(&g_bar, 1ULL);
        unsigned long long target = (old / NBLK + 1ULL) * NBLK;
        while (*(volatile unsigned long long*)&g_bar < target) { }
    }
    __syncthreads();
    // Phase-2 pooled reads use ld.global.cg (L2 is the coherence point).

    // ---------------- Phase 2: tiny GEMM (4 rows per block) ----------------
    const float inv = 1.0f / (float)HW;
    const int bk0 = blockIdx.x * ROWS_PER_BLOCK;

    float w0c[COLS_PER_THREAD], w1c[COLS_PER_THREAD], w2c[COLS_PER_THREAD];
    float bbc[COLS_PER_THREAD];
#pragma unroll
    for (int j = 0; j < COLS_PER_THREAD; j++) {
        int e = tid + j * TA;
        w0c[j] = Wmat[0 * Ex + e];
        w1c[j] = Wmat[1 * Ex + e];
        w2c[j] = Wmat[2 * Ex + e];
        bbc[j] = bias[e];
    }

#pragma unroll
    for (int r = 0; r < ROWS_PER_BLOCK; r++) {
        const int bk = bk0 + r;
        float4 p = ldcg4(&g_pool4[bk * ROW_F4]);   // broadcast load
        float p0 = p.x * inv, p1 = p.y * inv, p2 = p.z * inv;

#pragma unroll
        for (int j = 0; j < COLS_PER_THREAD; j++) {
            int e = tid + j * TA;
            float acc = bbc[j];
            acc = fmaf(p0, w0c[j], acc);
            acc = fmaf(p1, w1c[j], acc);
            acc = fmaf(p2, w2c[j], acc);
            out[(size_t)bk * Ex + e] = acc;
        }
    }

    // Restore the zero-invariant for the rows this block consumed
    // (only this block read them; global stores are write-through to L2).
    __syncthreads();
    if (tid < ROWS_PER_BLOCK) {
        g_pool4[(bk0 + tid) * ROW_F4] = make_float4(0.f, 0.f, 0.f, 0.f);
    }
}

extern "C" void kernel_launch(void* const* d_in, const int* in_sizes, int n_in,
                              void* d_out, int out_size) {
    const float* img  = (const float*)d_in[0];
    const int*   seg  = (const int*)d_in[1];
    const float* Wmat = (const float*)d_in[2];
    const float* bias = (const float*)d_in[3];
    float* out = (float*)d_out;

    fused_kernel<<<NBLK, TA>>>(img, seg, Wmat, bias, out);
}

// round 7
// speedup vs baseline: 1.1628x; 1.1628x over previous
#include <cuda_runtime.h>
#include <cuda_bf16.h>

// Problem constants
#define Bx 4
#define Cx 3
#define Hx 224
#define Wx 224
#define Kx 196
#define Ex 768
#define HW (Hx * Wx)               // 50176
#define KC (Kx * Cx)               // 588
#define BK (Bx * Kx)               // 784

#define BPB 49                     // accumulate blocks per batch
#define NBLK (Bx * BPB)            // 196 total blocks
#define TA 256
#define PIX_PER_BLOCK (TA * 4)     // 1024; 49*1024 = HW exactly

#define ROWS_PER_BLOCK (BK / NBLK) // 4
#define COLS_PER_THREAD (Ex / TA)  // 3

#define NREP 4                     // global-pool replicas (spread L2 atomic traffic)
#define ROW_F4 8                   // 128 B per (b,k) row

// Replicated pooled sums: g_pool4[rep][bk][ROW_F4]; only element 0 of each row
// used ({c0,c1,c2,pad}). Zero at module load; phase 2 re-zeroes consumed rows.
__device__ float4 g_pool4[NREP * BK * ROW_F4];

// Grid barrier: monotone epoch counter (never reset; u64 cannot overflow).
__device__ unsigned long long g_bar;

__device__ __forceinline__ void red_add_v4(float4* p, float x, float y, float z) {
    asm volatile("red.global.add.v4.f32 [%0], {%1, %2, %3, %4};"
                 :: "l"(p), "f"(x), "f"(y), "f"(z), "f"(0.0f) : "memory");
}

__device__ __forceinline__ float4 ldcg4(const float4* p) {
    float4 v;
    asm volatile("ld.global.cg.v4.f32 {%0,%1,%2,%3}, [%4];"
                 : "=f"(v.x), "=f"(v.y), "=f"(v.z), "=f"(v.w) : "l"(p));
    return v;
}

__global__ void fused_kernel(const float* __restrict__ img,
                             const int* __restrict__ seg,
                             const float* __restrict__ Wmat,
                             const float* __restrict__ bias,
                             float* __restrict__ out) {
    __shared__ float s_pool[KC];

    const int tid = threadIdx.x;
    const int b   = blockIdx.x / BPB;
    const int blk = blockIdx.x % BPB;
    const int rep = blockIdx.x & (NREP - 1);

    // ---------------- Phase 1: hybrid segment-sum ----------------
    for (int i = tid; i < KC; i += TA) s_pool[i] = 0.0f;
    __syncthreads();

    const int p0 = blk * PIX_PER_BLOCK + tid * 4;
    const float* img_b = img + (size_t)b * Cx * HW;
    const int*   seg_b = seg + (size_t)b * HW;

    int4   s  = *(const int4*)  (seg_b + p0);
    float4 v0 = *(const float4*)(img_b + p0);
    float4 v1 = *(const float4*)(img_b + p0 + HW);
    float4 v2 = *(const float4*)(img_b + p0 + 2 * HW);

    float4* pool_rb = g_pool4 + ((size_t)rep * BK + (size_t)b * Kx) * ROW_F4;

    // Pixels x,y -> shared-memory atomics (SM LSU unit)
    atomicAdd(&s_pool[s.x * Cx + 0], v0.x);
    atomicAdd(&s_pool[s.x * Cx + 1], v1.x);
    atomicAdd(&s_pool[s.x * Cx + 2], v2.x);
    atomicAdd(&s_pool[s.y * Cx + 0], v0.y);
    atomicAdd(&s_pool[s.y * Cx + 1], v1.y);
    atomicAdd(&s_pool[s.y * Cx + 2], v2.y);

    // Pixels z,w -> direct global vector reductions (L2 atomic ALU unit)
    red_add_v4(pool_rb + s.z * ROW_F4, v0.z, v1.z, v2.z);
    red_add_v4(pool_rb + s.w * ROW_F4, v0.w, v1.w, v2.w);

    __syncthreads();

    // Flush shared partials into this block's replica (one v4 RED per key)
    if (tid < Kx) {
        float c0 = s_pool[tid * Cx + 0];
        float c1 = s_pool[tid * Cx + 1];
        float c2 = s_pool[tid * Cx + 2];
        red_add_v4(pool_rb + tid * ROW_F4, c0, c1, c2);
    }

    // ---------------- Grid barrier (R4 form) ----------------
    __threadfence();                       // REDs visible before arrival RMW
    if (tid == 0) {
        unsigned long long old = atomicAdd(&g_bar, 1ULL);
        unsigned long long target = (old / NBLK + 1ULL) * NBLK;
        while (atomicAdd(&g_bar, 0ULL) < target) { }
    }
    __syncthreads();
    // Phase-2 pooled reads use ld.global.cg (L2 is the coherence point).

    // ---------------- Phase 2: tiny GEMM (4 rows per block) ----------------
    const float inv = 1.0f / (float)HW;
    const int bk0 = blockIdx.x * ROWS_PER_BLOCK;

    float w0c[COLS_PER_THREAD], w1c[COLS_PER_THREAD], w2c[COLS_PER_THREAD];
    float bbc[COLS_PER_THREAD];
#pragma unroll
    for (int j = 0; j < COLS_PER_THREAD; j++) {
        int e = tid + j * TA;
        w0c[j] = Wmat[0 * Ex + e];
        w1c[j] = Wmat[1 * Ex + e];
        w2c[j] = Wmat[2 * Ex + e];
        bbc[j] = bias[e];
    }

#pragma unroll
    for (int r = 0; r < ROWS_PER_BLOCK; r++) {
        const int bk = bk0 + r;
        float p0 = 0.f, p1 = 0.f, p2 = 0.f;
#pragma unroll
        for (int rp = 0; rp < NREP; rp++) {
            float4 p = ldcg4(&g_pool4[((size_t)rp * BK + bk) * ROW_F4]);
            p0 += p.x; p1 += p.y; p2 += p.z;
        }
        p0 *= inv; p1 *= inv; p2 *= inv;

#pragma unroll
        for (int j = 0; j < COLS_PER_THREAD; j++) {
            int e = tid + j * TA;
            float acc = bbc[j];
            acc = fmaf(p0, w0c[j], acc);
            acc = fmaf(p1, w1c[j], acc);
            acc = fmaf(p2, w2c[j], acc);
            out[(size_t)bk * Ex + e] = acc;
        }
    }

    // Restore the zero-invariant for all replicas of the rows this block read.
    __syncthreads();
    if (tid < ROWS_PER_BLOCK * NREP) {
        int rp  = tid / ROWS_PER_BLOCK;
        int row = bk0 + (tid % ROWS_PER_BLOCK);
        g_pool4[((size_t)rp * BK + row) * ROW_F4] = make_float4(0.f, 0.f, 0.f, 0.f);
    }
}

extern "C" void kernel_launch(void* const* d_in, const int* in_sizes, int n_in,
                              void* d_out, int out_size) {
    const float* img  = (const float*)d_in[0];
    const int*   seg  = (const int*)d_in[1];
    const float* Wmat = (const float*)d_in[2];
    const float* bias = (const float*)d_in[3];
    float* out = (float*)d_out;

    fused_kernel<<<NBLK, TA>>>(img, seg, Wmat, bias, out);
}